// round 1
// baseline (speedup 1.0000x reference)
#include <cuda_runtime.h>

// Problem shape (fixed by the dataset)
#define BB 128
#define PP 4096
#define NN 64

// Precomputed per-center coefficients:
// q[n](x) = K_n + a0*x0^2 + b0*x0 + a1*x1^2 + b1*x1  where EX2(q) = exp(-dist)
// a0 = -log2e*s0^2, b0 = -2*a0*c0, K = a0*c0^2 + a1*c1^2
__device__ float4 g_cab[NN];   // {a0, b0, a1, b1}
__device__ float  g_k[NN];

__global__ void slayer_precompute(const float* __restrict__ centers,
                                  const float* __restrict__ sharp) {
    int n = threadIdx.x;
    if (n < NN) {
        const float L = 1.4426950408889634f;  // log2(e)
        float c0 = centers[2 * n], c1 = centers[2 * n + 1];
        float s0 = sharp[2 * n],   s1 = sharp[2 * n + 1];
        float a0 = -L * s0 * s0;
        float a1 = -L * s1 * s1;
        float b0 = -2.0f * a0 * c0;
        float b1 = -2.0f * a1 * c1;
        float K  = a0 * c0 * c0 + a1 * c1 * c1;
        g_cab[n] = make_float4(a0, b0, a1, b1);
        g_k[n]   = K;
    }
}

// One block per batch b. 512 threads = 16 warps.
//   warp & 7  -> which block of 8 centers this warp owns (coeffs in registers)
//   warp >> 3 -> which half of the P=4096 points this warp sweeps
// Each (p,n): 4 FFMA poly + EX2 + 1 FFMA masked accumulate.
__global__ __launch_bounds__(512, 1) void slayer_main(
    const float2* __restrict__ batch,   // [B, P] of float2 (D=2)
    const float*  __restrict__ mask,    // [B, P]
    float*        __restrict__ out)     // [B, N]
{
    const int b    = blockIdx.x;
    const int tid  = threadIdx.x;
    const int warp = tid >> 5;
    const int lane = tid & 31;
    const int nb   = warp & 7;    // center block (8 centers)
    const int half = warp >> 3;   // point half

    // Register-resident coefficients for this warp's 8 centers
    float4 cab[8];
    float  kk[8];
#pragma unroll
    for (int j = 0; j < 8; j++) {
        cab[j] = g_cab[nb * 8 + j];
        kk[j]  = g_k[nb * 8 + j];
    }

    float acc[8];
#pragma unroll
    for (int j = 0; j < 8; j++) acc[j] = 0.0f;

    const float2* bp = batch + (size_t)b * PP;
    const float*  mp = mask  + (size_t)b * PP;

    const int p0 = half * (PP / 2) + lane;
    constexpr int ITERS = (PP / 2) / 32;   // 64

#pragma unroll 4
    for (int it = 0; it < ITERS; it++) {
        const int p = p0 + it * 32;
        const float2 x = __ldg(bp + p);
        const float  m = __ldg(mp + p);
        const float x00 = x.x * x.x;
        const float x11 = x.y * x.y;
#pragma unroll
        for (int j = 0; j < 8; j++) {
            float q = kk[j];
            q = fmaf(cab[j].x, x00, q);
            q = fmaf(cab[j].y, x.x, q);
            q = fmaf(cab[j].z, x11, q);
            q = fmaf(cab[j].w, x.y, q);
            float e;
            asm("ex2.approx.ftz.f32 %0, %1;" : "=f"(e) : "f"(q));
            acc[j] = fmaf(m, e, acc[j]);
        }
    }

    // Intra-warp reduce over the 32 point-lanes
#pragma unroll
    for (int off = 16; off > 0; off >>= 1) {
#pragma unroll
        for (int j = 0; j < 8; j++)
            acc[j] += __shfl_xor_sync(0xffffffffu, acc[j], off);
    }

    // Combine the two point-halves deterministically via shared memory
    __shared__ float partial[2][NN];
    if (lane == 0) {
#pragma unroll
        for (int j = 0; j < 8; j++)
            partial[half][nb * 8 + j] = acc[j];
    }
    __syncthreads();

    if (tid < NN)
        out[b * NN + tid] = partial[0][tid] + partial[1][tid];
}

extern "C" void kernel_launch(void* const* d_in, const int* in_sizes, int n_in,
                              void* d_out, int out_size) {
    const float* batch   = (const float*)d_in[0];   // [B,P,D] f32
    const float* mask    = (const float*)d_in[1];   // [B,P]   f32
    const float* centers = (const float*)d_in[2];   // [N,D]   f32
    const float* sharp   = (const float*)d_in[3];   // [N,D]   f32
    float* out = (float*)d_out;                     // [B,N]   f32

    slayer_precompute<<<1, 64>>>(centers, sharp);
    slayer_main<<<BB, 512>>>((const float2*)batch, mask, out);
}